// round 4
// baseline (speedup 1.0000x reference)
#include <cuda_runtime.h>

// SpatialDeformer3D via SMEM-tiled trilinear gather.
//   X:           (2, 160, 192, 160, 2)  float32
//   deformation: (2, 160, 192, 160, 3)  float32
//   out:         (2, 160, 192, 160, 1)  float32
//
// Each CTA computes a 16x16x32 (h,w,d) output tile. Channel 0 of X for the
// tile + a 4/5-voxel halo is staged in SMEM (border-clipped, matching the
// reference's clip semantics). Taps with |def| < 4 (essentially all, since
// def ~ N(0,1)) resolve from SMEM; the rare out-of-halo tap falls back to
// global loads (bit-identical math on both paths).

#define BB 2
#define HH 160
#define WW 192
#define DD 160

#define TH 16
#define TW 16
#define TD 32
#define RLO 4            // halo below; +5 above (x1 = x0+1) => extent T+9
#define HS (TH + 9)      // 25
#define WS (TW + 9)      // 25
#define DS (TD + 9)      // 41
#define SVOL (HS * WS * DS)   // 25625 floats = 102500 B

__global__ __launch_bounds__(512, 2) void deform3d_tile_kernel(
    const float* __restrict__ X,
    const float* __restrict__ def,
    float* __restrict__ out)
{
    extern __shared__ float s[];

    const int b  = blockIdx.z / (HH / TH);
    const int hz = blockIdx.z % (HH / TH);
    const int h0 = hz * TH;
    const int w0 = blockIdx.y * TW;
    const int d0 = blockIdx.x * TD;

    const int tid = threadIdx.y * 32 + threadIdx.x;   // 512 threads

    const float* Xb = X + (size_t)b * (HH * WW * DD * 2);

    const int yb = h0 - RLO;
    const int xb = w0 - RLO;
    const int zb = d0 - RLO;

    // ---- Fill SMEM tile (border-clipped channel 0 of X) ----
    for (int i = tid; i < SVOL; i += 512) {
        int dz = i % DS;
        int r  = i / DS;
        int wx = r % WS;
        int hy = r / WS;
        int gy = min(max(yb + hy, 0), HH - 1);
        int gx = min(max(xb + wx, 0), WW - 1);
        int gz = min(max(zb + dz, 0), DD - 1);
        s[i] = __ldg(Xb + ((gy * WW + gx) * DD + gz) * 2);
    }
    __syncthreads();

    const int d = d0 + threadIdx.x;   // lane -> d : coalesced def/out
    const int w = w0 + threadIdx.y;

    #pragma unroll 2
    for (int hh = 0; hh < TH; hh++) {
        const int h = h0 + hh;
        const int vox = ((b * HH + h) * WW + w) * DD + d;

        const float* dp = def + (size_t)vox * 3;
        float dx = __ldg(dp + 0);
        float dy = __ldg(dp + 1);
        float dzv = __ldg(dp + 2);

        float x = (float)w + dx;   // def[...,0] -> W axis
        float y = (float)h + dy;   // def[...,1] -> H axis
        float z = (float)d + dzv;  // def[...,2] -> D axis

        int x0 = (int)floorf(x), y0 = (int)floorf(y), z0 = (int)floorf(z);
        int x1 = x0 + 1, y1 = y0 + 1, z1 = z0 + 1;

        // Reference semantics: clip each corner independently; weights from
        // the CLIPPED coords so out-of-range dims cancel to zero.
        x0 = min(max(x0, 0), WW - 1);  x1 = min(max(x1, 0), WW - 1);
        y0 = min(max(y0, 0), HH - 1);  y1 = min(max(y1, 0), HH - 1);
        z0 = min(max(z0, 0), DD - 1);  z1 = min(max(z1, 0), DD - 1);

        float wx0 = (float)x1 - x, wx1 = x - (float)x0;
        float wy0 = (float)y1 - y, wy1 = y - (float)y0;
        float wz0 = (float)z1 - z, wz1 = z - (float)z0;

        int sy0 = y0 - yb, sy1 = y1 - yb;
        int sx0 = x0 - xb, sx1 = x1 - xb;
        int sz0 = z0 - zb, sz1 = z1 - zb;

        bool in_tile = ((unsigned)sy0 < HS) & ((unsigned)sy1 < HS) &
                       ((unsigned)sx0 < WS) & ((unsigned)sx1 < WS) &
                       ((unsigned)sz0 < DS) & ((unsigned)sz1 < DS);

        float p000, p001, p010, p011, p100, p101, p110, p111;
        if (in_tile) {
            int r00 = (sy0 * WS + sx0) * DS;
            int r01 = (sy0 * WS + sx1) * DS;
            int r10 = (sy1 * WS + sx0) * DS;
            int r11 = (sy1 * WS + sx1) * DS;
            p000 = s[r00 + sz0];  p001 = s[r00 + sz1];
            p010 = s[r01 + sz0];  p011 = s[r01 + sz1];
            p100 = s[r10 + sz0];  p101 = s[r10 + sz1];
            p110 = s[r11 + sz0];  p111 = s[r11 + sz1];
        } else {
            int i00 = ((y0 * WW + x0) * DD) * 2;
            int i01 = ((y0 * WW + x1) * DD) * 2;
            int i10 = ((y1 * WW + x0) * DD) * 2;
            int i11 = ((y1 * WW + x1) * DD) * 2;
            int z0e = z0 * 2, z1e = z1 * 2;
            p000 = __ldg(Xb + i00 + z0e);  p001 = __ldg(Xb + i00 + z1e);
            p010 = __ldg(Xb + i01 + z0e);  p011 = __ldg(Xb + i01 + z1e);
            p100 = __ldg(Xb + i10 + z0e);  p101 = __ldg(Xb + i10 + z1e);
            p110 = __ldg(Xb + i11 + z0e);  p111 = __ldg(Xb + i11 + z1e);
        }

        float res = wy0 * (wx0 * (wz0 * p000 + wz1 * p001) +
                           wx1 * (wz0 * p010 + wz1 * p011)) +
                    wy1 * (wx0 * (wz0 * p100 + wz1 * p101) +
                           wx1 * (wz0 * p110 + wz1 * p111));

        out[vox] = res;
    }
}

extern "C" void kernel_launch(void* const* d_in, const int* in_sizes, int n_in,
                              void* d_out, int out_size)
{
    const float* X   = (const float*)d_in[0];
    const float* def = (const float*)d_in[1];
    float* out = (float*)d_out;

    cudaFuncSetAttribute(deform3d_tile_kernel,
                         cudaFuncAttributeMaxDynamicSharedMemorySize,
                         SVOL * (int)sizeof(float));

    dim3 grid(DD / TD, WW / TW, BB * (HH / TH));   // (5, 12, 20) = 1200 CTAs
    dim3 block(32, 16, 1);                          // 512 threads
    deform3d_tile_kernel<<<grid, block, SVOL * sizeof(float)>>>(X, def, out);
}

// round 5
// speedup vs baseline: 1.1602x; 1.1602x over previous
#include <cuda_runtime.h>

// SpatialDeformer3D via SMEM-tiled trilinear gather, v2:
//  - warp-per-row SMEM fill (amortized index math, hoisted z-clamp)
//  - 8x16x32 tile (69.7KB smem) -> 3 CTAs/SM, 48 warps
//
//   X:           (2, 160, 192, 160, 2)  float32
//   deformation: (2, 160, 192, 160, 3)  float32
//   out:         (2, 160, 192, 160, 1)  float32

#define BB 2
#define HH 160
#define WW 192
#define DD 160
#define WD (WW * DD)

#define TH 8
#define TW 16
#define TD 32
#define RLO 4              // halo below; +5 above => extent T+9
#define HS (TH + 9)        // 17
#define WS (TW + 9)        // 25
#define DS (TD + 9)        // 41
#define NROWS (HS * WS)    // 425
#define SVOL (NROWS * DS)  // 17425 floats = 69700 B

__global__ __launch_bounds__(512, 3) void deform3d_tile2_kernel(
    const float* __restrict__ X,
    const float* __restrict__ def,
    float* __restrict__ out)
{
    extern __shared__ float s[];

    const int b  = blockIdx.z / (HH / TH);
    const int hz = blockIdx.z % (HH / TH);
    const int h0 = hz * TH;
    const int w0 = blockIdx.y * TW;
    const int d0 = blockIdx.x * TD;

    const int lane = threadIdx.x;          // 0..31  -> d
    const int wy   = threadIdx.y;          // 0..15  -> w
    const int warpId = wy;                 // 16 warps

    const float* Xb = X + (size_t)b * (HH * WW * DD * 2);

    const int yb = h0 - RLO;
    const int xb = w0 - RLO;
    const int zb = d0 - RLO;

    // ---- SMEM fill: one warp per (hy,wx) row of DS=41 elements ----
    // z-clamp is row-invariant per lane: hoist it.
    const int ezA = min(max(zb + lane, 0), DD - 1) * 2;            // pass 1
    const int ezB = min(max(zb + lane + 32, 0), DD - 1) * 2;       // pass 2 (lane<9)

    for (int row = warpId; row < NROWS; row += 16) {
        int hy = row / WS;
        int wx = row - hy * WS;
        int gy = min(max(yb + hy, 0), HH - 1);
        int gx = min(max(xb + wx, 0), WW - 1);
        const float* src = Xb + (size_t)(gy * WW + gx) * (DD * 2);
        float* dst = s + row * DS;
        dst[lane] = __ldg(src + ezA);
        if (lane < DS - 32)
            dst[lane + 32] = __ldg(src + ezB);
    }
    __syncthreads();

    const int d = d0 + lane;
    const int w = w0 + wy;

    int vox = ((b * HH + h0) * WW + w) * DD + d;
    const float* dp = def + (size_t)vox * 3;
    const float wf = (float)w;
    const float df = (float)d;

    #pragma unroll
    for (int hh = 0; hh < TH; hh++, vox += WD, dp += (size_t)WD * 3) {
        const int h = h0 + hh;

        float dx  = __ldg(dp + 0);
        float dy  = __ldg(dp + 1);
        float dzv = __ldg(dp + 2);

        float x = wf + dx;          // def[...,0] -> W axis
        float y = (float)h + dy;    // def[...,1] -> H axis
        float z = df + dzv;         // def[...,2] -> D axis

        int x0 = (int)floorf(x), y0 = (int)floorf(y), z0 = (int)floorf(z);
        int x1 = x0 + 1, y1 = y0 + 1, z1 = z0 + 1;

        // Reference semantics: clip each corner independently; weights from
        // CLIPPED coords so out-of-range dims cancel to zero.
        x0 = min(max(x0, 0), WW - 1);  x1 = min(max(x1, 0), WW - 1);
        y0 = min(max(y0, 0), HH - 1);  y1 = min(max(y1, 0), HH - 1);
        z0 = min(max(z0, 0), DD - 1);  z1 = min(max(z1, 0), DD - 1);

        float wx0 = (float)x1 - x, wx1 = x - (float)x0;
        float wy0 = (float)y1 - y, wy1 = y - (float)y0;
        float wz0 = (float)z1 - z, wz1 = z - (float)z0;

        int sy0 = y0 - yb, sy1 = y1 - yb;
        int sx0 = x0 - xb, sx1 = x1 - xb;
        int sz0 = z0 - zb, sz1 = z1 - zb;

        bool in_tile = ((unsigned)sy0 < HS) & ((unsigned)sy1 < HS) &
                       ((unsigned)sx0 < WS) & ((unsigned)sx1 < WS) &
                       ((unsigned)sz0 < DS) & ((unsigned)sz1 < DS);

        float p000, p001, p010, p011, p100, p101, p110, p111;
        if (in_tile) {
            int r00 = (sy0 * WS + sx0) * DS;
            int r01 = (sy0 * WS + sx1) * DS;
            int r10 = (sy1 * WS + sx0) * DS;
            int r11 = (sy1 * WS + sx1) * DS;
            p000 = s[r00 + sz0];  p001 = s[r00 + sz1];
            p010 = s[r01 + sz0];  p011 = s[r01 + sz1];
            p100 = s[r10 + sz0];  p101 = s[r10 + sz1];
            p110 = s[r11 + sz0];  p111 = s[r11 + sz1];
        } else {
            int i00 = (y0 * WW + x0) * (DD * 2);
            int i01 = (y0 * WW + x1) * (DD * 2);
            int i10 = (y1 * WW + x0) * (DD * 2);
            int i11 = (y1 * WW + x1) * (DD * 2);
            int z0e = z0 * 2, z1e = z1 * 2;
            p000 = __ldg(Xb + i00 + z0e);  p001 = __ldg(Xb + i00 + z1e);
            p010 = __ldg(Xb + i01 + z0e);  p011 = __ldg(Xb + i01 + z1e);
            p100 = __ldg(Xb + i10 + z0e);  p101 = __ldg(Xb + i10 + z1e);
            p110 = __ldg(Xb + i11 + z0e);  p111 = __ldg(Xb + i11 + z1e);
        }

        float res = wy0 * (wx0 * (wz0 * p000 + wz1 * p001) +
                           wx1 * (wz0 * p010 + wz1 * p011)) +
                    wy1 * (wx0 * (wz0 * p100 + wz1 * p101) +
                           wx1 * (wz0 * p110 + wz1 * p111));

        out[vox] = res;
    }
}

extern "C" void kernel_launch(void* const* d_in, const int* in_sizes, int n_in,
                              void* d_out, int out_size)
{
    const float* X   = (const float*)d_in[0];
    const float* def = (const float*)d_in[1];
    float* out = (float*)d_out;

    cudaFuncSetAttribute(deform3d_tile2_kernel,
                         cudaFuncAttributeMaxDynamicSharedMemorySize,
                         SVOL * (int)sizeof(float));

    dim3 grid(DD / TD, WW / TW, BB * (HH / TH));   // (5, 12, 40) = 2400 CTAs
    dim3 block(32, 16, 1);                          // 512 threads
    deform3d_tile2_kernel<<<grid, block, SVOL * sizeof(float)>>>(X, def, out);
}